// round 14
// baseline (speedup 1.0000x reference)
#include <cuda_runtime.h>
#include <cuda_fp16.h>
#include <cstdint>

constexpr int NN = 10000;
constexpr int NE = 160000;
constexpr float HSTEP = 0.1f;
constexpr float FSCALE = 256.0f;
constexpr float FINV = 1.0f / 256.0f;

__device__ float g_xn[NN * 128];
__device__ float g_xe[(size_t)NE * 128];
__device__ float g_ya[NN * 128];
__device__ float g_yb[NN * 128];
__device__ uint32_t g_fluxh[(size_t)NE * 64];
__device__ uint32_t g_aveh[NN * 64];
__device__ uint32_t g_divh[NN * 64];
__device__ int g_rowptr[NN + 1];
__device__ int g_cursor[NN];
__device__ int g_elist[2 * NE];
// 37 sections x 32KB fp16 (pre-swizzled): [0..15] edge (Wa,Wb,Wxe,W2)x4,
// [16..31] node (ave,div,xn,W2)x4, [32,33] openN, [34,35] openE, [36] close
__device__ uint8_t g_wpack[37 * 32768];

// ---------------- CSR build ----------------
__global__ void k_zero_cursor() {
    int i = blockIdx.x * blockDim.x + threadIdx.x;
    if (i < NN) g_cursor[i] = 0;
}
__global__ void k_deg(const int* __restrict__ iInd, const int* __restrict__ jInd) {
    int e = blockIdx.x * blockDim.x + threadIdx.x;
    if (e < NE) { atomicAdd(&g_cursor[iInd[e]], 1); atomicAdd(&g_cursor[jInd[e]], 1); }
}
__global__ void k_scan() {
    __shared__ int part[1024];
    const int t = threadIdx.x;
    constexpr int CH = (NN + 1023) / 1024;
    int base = t * CH, loc[CH], s = 0;
    #pragma unroll
    for (int k = 0; k < CH; k++) {
        int idx = base + k;
        int v = (idx < NN) ? g_cursor[idx] : 0;
        loc[k] = s; s += v;
    }
    part[t] = s;
    __syncthreads();
    for (int off = 1; off < 1024; off <<= 1) {
        int v = 0;
        if (t >= off) v = part[t - off];
        __syncthreads();
        if (t >= off) part[t] += v;
        __syncthreads();
    }
    int pre = (t == 0) ? 0 : part[t - 1];
    #pragma unroll
    for (int k = 0; k < CH; k++) {
        int idx = base + k;
        if (idx < NN) { int rp = pre + loc[k]; g_rowptr[idx] = rp; g_cursor[idx] = rp; }
    }
    if (t == 1023) g_rowptr[NN] = part[1023];
}
__global__ void k_fill(const int* __restrict__ iInd, const int* __restrict__ jInd) {
    int e = blockIdx.x * blockDim.x + threadIdx.x;
    if (e < NE) {
        int p = atomicAdd(&g_cursor[iInd[e]], 1); g_elist[p] = 2 * e;
        int q = atomicAdd(&g_cursor[jInd[e]], 1); g_elist[q] = 2 * e + 1;
    }
}

// ---------------- helpers ----------------
__device__ __forceinline__ uint32_t smem_u32(const void* p) {
    uint32_t a;
    asm("{ .reg .u64 t; cvta.to.shared.u64 t, %1; cvt.u32.u64 %0, t; }" : "=r"(a) : "l"(p));
    return a;
}
__host__ __device__ __forceinline__ uint32_t toff(int row, int k) {
    return (uint32_t)(row * 256) + (uint32_t)((((((k >> 3)) ^ row) & 15) << 4) | ((k & 7) * 2));
}
__device__ __forceinline__ uint32_t h2pack(float a, float b) {
    __half2 hh = __floats2half2_rn(a, b);
    return *reinterpret_cast<uint32_t*>(&hh);
}
__device__ __forceinline__ float2 h2unpack(uint32_t v) {
    return __half22float2(*reinterpret_cast<__half2*>(&v));
}
__device__ __forceinline__ void stX8(char* buf, int row, int k, float4 a, float4 b) {
    *reinterpret_cast<uint4*>(buf + toff(row, k)) =
        make_uint4(h2pack(a.x, a.y), h2pack(a.z, a.w), h2pack(b.x, b.y), h2pack(b.z, b.w));
}
__device__ __forceinline__ void ldmx4(uint32_t* r, uint32_t a) {
    asm volatile("ldmatrix.sync.aligned.m8n8.x4.shared.b16 {%0,%1,%2,%3}, [%4];"
                 : "=r"(r[0]), "=r"(r[1]), "=r"(r[2]), "=r"(r[3]) : "r"(a));
}
__device__ __forceinline__ void mma16816(float* d, const uint32_t* a, uint32_t b0, uint32_t b1) {
    asm volatile(
        "mma.sync.aligned.m16n8k16.row.col.f32.f16.f16.f32 "
        "{%0,%1,%2,%3},{%4,%5,%6,%7},{%8,%9},{%0,%1,%2,%3};"
        : "+f"(d[0]), "+f"(d[1]), "+f"(d[2]), "+f"(d[3])
        : "r"(a[0]), "r"(a[1]), "r"(a[2]), "r"(a[3]), "r"(b0), "r"(b1));
}
template <int NT>
__device__ __forceinline__ void cpWasync(uint32_t wsm, int sec, int t) {
    const char* src = reinterpret_cast<const char*>(g_wpack) + (size_t)sec * 32768 + t * 16;
    uint32_t dst = wsm + t * 16;
    #pragma unroll
    for (int i = 0; i < 2048 / NT; i++)
        asm volatile("cp.async.cg.shared.global [%0], [%1], 16;"
                     :: "r"(dst + i * NT * 16), "l"(src + i * NT * 16) : "memory");
    asm volatile("cp.async.commit_group;" ::: "memory");
}
template <int N>
__device__ __forceinline__ void cp_wait() {
    asm volatile("cp.async.wait_group %0;" :: "n"(N) : "memory");
}

template <int NBLK, int KS>
__device__ __forceinline__ void gemmX(uint32_t xa, uint32_t wa, int m0, int lane, float acc[][4]) {
    #pragma unroll
    for (int ks = 0; ks < KS; ks++) {
        int k0 = ks * 16;
        uint32_t ah[4];
        ldmx4(ah, xa + toff(m0 + (lane & 15), k0 + ((lane >> 4) << 3)));
        #pragma unroll
        for (int p = 0; p < NBLK / 2; p++) {
            uint32_t bh[4];
            ldmx4(bh, wa + toff(p * 16 + (lane & 7) + ((lane >> 4) << 3),
                                k0 + (((lane >> 3) & 1) << 3)));
            mma16816(acc[2 * p],     ah, bh[0], bh[1]);
            mma16816(acc[2 * p + 1], ah, bh[2], bh[3]);
        }
    }
}
// D1 frag acc[nb]={D[m][c],D[m][c+1],D[m+8][c],D[m+8][c+1]}; A2 frag per ks:
// a0=acc[2ks][0,1], a1=acc[2ks][2,3], a2=acc[2ks+1][0,1], a3=acc[2ks+1][2,3].
__device__ __forceinline__ void pack_tanh(const float acc[][4], uint32_t* af) {
    #pragma unroll
    for (int ks = 0; ks < 8; ks++) {
        af[4 * ks + 0] = h2pack(tanhf(acc[2 * ks][0]),     tanhf(acc[2 * ks][1]));
        af[4 * ks + 1] = h2pack(tanhf(acc[2 * ks][2]),     tanhf(acc[2 * ks][3]));
        af[4 * ks + 2] = h2pack(tanhf(acc[2 * ks + 1][0]), tanhf(acc[2 * ks + 1][1]));
        af[4 * ks + 3] = h2pack(tanhf(acc[2 * ks + 1][2]), tanhf(acc[2 * ks + 1][3]));
    }
}
__device__ __forceinline__ void pack_id(const float acc[][4], uint32_t* af) {
    #pragma unroll
    for (int ks = 0; ks < 8; ks++) {
        af[4 * ks + 0] = h2pack(acc[2 * ks][0],     acc[2 * ks][1]);
        af[4 * ks + 1] = h2pack(acc[2 * ks][2],     acc[2 * ks][3]);
        af[4 * ks + 2] = h2pack(acc[2 * ks + 1][0], acc[2 * ks + 1][1]);
        af[4 * ks + 3] = h2pack(acc[2 * ks + 1][2], acc[2 * ks + 1][3]);
    }
}
template <int NP>
__device__ __forceinline__ void gemm2t(const uint32_t* af, uint32_t wa, int lane, float acc2[][4]) {
    #pragma unroll
    for (int ks = 0; ks < 8; ks++) {
        int k0 = ks * 16;
        #pragma unroll
        for (int p = 0; p < NP; p++) {
            uint32_t bh[4];
            ldmx4(bh, wa + toff(p * 16 + (lane & 7) + ((lane >> 4) << 3),
                                k0 + (((lane >> 3) & 1) << 3)));
            mma16816(acc2[2 * p],     af + 4 * ks, bh[0], bh[1]);
            mma16816(acc2[2 * p + 1], af + 4 * ks, bh[2], bh[3]);
        }
    }
}
__device__ __forceinline__ void store_y(float* dstbuf, const float acc[][4],
                                        int n0, int m0, int lane) {
    int r = m0 + (lane >> 2);
    int na = n0 + r, nb2 = n0 + r + 8;
    #pragma unroll
    for (int nb = 0; nb < 16; nb++) {
        int c = nb * 8 + (lane & 3) * 2;
        if (na < NN)  *reinterpret_cast<float2*>(dstbuf + (size_t)na * 128 + c) =
            make_float2(acc[nb][0], acc[nb][1]);
        if (nb2 < NN) *reinterpret_cast<float2*>(dstbuf + (size_t)nb2 * 128 + c) =
            make_float2(acc[nb][2], acc[nb][3]);
    }
}

// ---------------- flux -> dense ave/div, 4-way unrolled CSR loop ----------------
__device__ __forceinline__ void acc_edge(int v, int p0, float2* s, float2* d) {
    int e = v >> 1;
    float sg = (v & 1) ? -1.f : 1.f;
    const uint4* f4 = (const uint4*)(g_fluxh + (size_t)e * 64 + p0);
    uint4 a = f4[0], b = f4[1];
    uint32_t wds[8] = {a.x, a.y, a.z, a.w, b.x, b.y, b.z, b.w};
    #pragma unroll
    for (int q = 0; q < 8; q++) {
        float2 f = h2unpack(wds[q]);
        s[q].x += f.x; s[q].y += f.y;
        d[q].x = fmaf(sg, f.x, d[q].x);
        d[q].y = fmaf(sg, f.y, d[q].y);
    }
}
__global__ void __launch_bounds__(256) k_gather() {
    int t = threadIdx.x;
    int node = blockIdx.x * 32 + (t >> 3);
    int p0 = (t & 7) * 8;
    if (node >= NN) return;
    float2 s[8], d[8];
    #pragma unroll
    for (int q = 0; q < 8; q++) { s[q] = make_float2(0.f, 0.f); d[q] = make_float2(0.f, 0.f); }
    int beg = g_rowptr[node], end = g_rowptr[node + 1];
    int p = beg;
    for (; p + 4 <= end; p += 4) {
        int v0 = g_elist[p], v1 = g_elist[p + 1], v2 = g_elist[p + 2], v3 = g_elist[p + 3];
        acc_edge(v0, p0, s, d);
        acc_edge(v1, p0, s, d);
        acc_edge(v2, p0, s, d);
        acc_edge(v3, p0, s, d);
    }
    for (; p < end; p++) acc_edge(g_elist[p], p0, s, d);
    uint32_t oa[8], od[8];
    #pragma unroll
    for (int q = 0; q < 8; q++) {
        oa[q] = h2pack(s[q].x * (0.5f * FINV), s[q].y * (0.5f * FINV));
        od[q] = h2pack(d[q].x * FINV, d[q].y * FINV);
    }
    uint4* pa = (uint4*)(g_aveh + (size_t)node * 64 + p0);
    uint4* pd = (uint4*)(g_divh + (size_t)node * 64 + p0);
    pa[0] = make_uint4(oa[0], oa[1], oa[2], oa[3]);
    pa[1] = make_uint4(oa[4], oa[5], oa[6], oa[7]);
    pd[0] = make_uint4(od[0], od[1], od[2], od[3]);
    pd[1] = make_uint4(od[4], od[5], od[6], od[7]);
}

// ---------------- weight pre-pack ----------------
__global__ void k_pack(const float* __restrict__ KE1, const float* __restrict__ KE2,
                       const float* __restrict__ KN1, const float* __restrict__ KN2,
                       const float* __restrict__ K1N, const float* __restrict__ K2N,
                       const float* __restrict__ K1E, const float* __restrict__ K2E,
                       const float* __restrict__ KNc) {
    int sec = blockIdx.x;
    uint8_t* dst = g_wpack + (size_t)sec * 32768;
    for (int v = threadIdx.x; v < 16384; v += 256) {
        int o = v >> 7, c = v & 127;
        float val = 0.f;
        if (sec < 16) {
            int l = sec >> 2, kd = sec & 3;
            const float* E1 = KE1 + (size_t)l * 128 * 384;
            if (kd == 0)      val = 0.5f * E1[o * 384 + c] + E1[o * 384 + 256 + c];
            else if (kd == 1) val = 0.5f * E1[o * 384 + c] - E1[o * 384 + 256 + c];
            else if (kd == 2) val = E1[o * 384 + 128 + c];
            else              val = KE2[(size_t)l * 16384 + o * 128 + c];
        } else if (sec < 32) {
            int l = (sec - 16) >> 2, kd = sec & 3;
            const float* N1 = KN1 + (size_t)l * 128 * 384;
            if (kd == 0)      val = N1[o * 384 + c];
            else if (kd == 1) val = N1[o * 384 + 128 + c];
            else if (kd == 2) val = N1[o * 384 + 256 + c];
            else              val = KN2[(size_t)l * 16384 + o * 128 + c];
        } else if (sec == 32) { val = (c < 64) ? K1N[o * 64 + c] : 0.f; }
        else if (sec == 33)   { val = K2N[o * 128 + c]; }
        else if (sec == 34)   { val = (c < 64) ? K1E[o * 64 + c] : 0.f; }
        else if (sec == 35)   { val = K2E[o * 128 + c]; }
        else                  { val = (o < 64) ? KNc[o * 128 + c] : 0.f; }
        *reinterpret_cast<__half*>(dst + toff(o, c)) = __float2half(val);
    }
}

// MODE: 0 openN (+ya/yb l0), 4 openE, 1 edge
template <int MODE>
__global__ void __launch_bounds__(128, (MODE == 4 || MODE == 1) ? 4 : 2)
mm2_layer(int sec0, int secN, const float* __restrict__ src, float* __restrict__ dst,
          const int* __restrict__ iInd, const int* __restrict__ jInd, int ncols) {
    constexpr int MT = 64;
    constexpr int NT = 128;
    constexpr uint32_t XB = 16384;
    extern __shared__ char sm[];
    char* X0 = sm;
    const uint32_t sb = smem_u32(sm);
    const uint32_t aX0 = sb;
    const uint32_t aW  = sb + XB;
    const uint32_t aW1 = aW + 32768u;   // openN only

    const int t = threadIdx.x, lane = t & 31, w = t >> 5;
    const int n0 = blockIdx.x * MT;
    const int ln = t >> 1, cg = t & 1, c0 = cg * 64;
    const int m0 = w * 16;

    float acc[16][4];
    #pragma unroll
    for (int i = 0; i < 16; i++) { acc[i][0] = acc[i][1] = acc[i][2] = acc[i][3] = 0.f; }

    if constexpr (MODE == 0 || MODE == 4) {
        cpWasync<NT>(aW, sec0, t);
        if (MODE == 0) cpWasync<NT>(aW1, sec0 + 1, t);
        int n = n0 + ln;
        bool valid = (MODE == 4) || (n < ncols);
        int ns = valid ? n : 0;
        int kb = cg * 32;
        #pragma unroll
        for (int u = 0; u < 4; u++) {
            float4 a = make_float4(0.f, 0.f, 0.f, 0.f), b = a;
            if (valid) {
                int c = kb + u * 8;
                a.x = src[(size_t)(c + 0) * ncols + ns]; a.y = src[(size_t)(c + 1) * ncols + ns];
                a.z = src[(size_t)(c + 2) * ncols + ns]; a.w = src[(size_t)(c + 3) * ncols + ns];
                b.x = src[(size_t)(c + 4) * ncols + ns]; b.y = src[(size_t)(c + 5) * ncols + ns];
                b.z = src[(size_t)(c + 6) * ncols + ns]; b.w = src[(size_t)(c + 7) * ncols + ns];
            }
            stX8(X0, ln, kb + u * 8, a, b);
        }
        cp_wait<0>(); __syncthreads();
        gemmX<16, 4>(aX0, aW, m0, lane, acc);
        uint32_t af[32];
        pack_tanh(acc, af);
        uint32_t w2a = aW;
        if (MODE == 0) {
            w2a = aW1;
        } else {
            __syncthreads();
            cpWasync<NT>(aW, sec0 + 1, t);
            cp_wait<0>(); __syncthreads();
        }
        float acc2[16][4];
        #pragma unroll
        for (int i = 0; i < 16; i++) { acc2[i][0] = acc2[i][1] = acc2[i][2] = acc2[i][3] = 0.f; }
        gemm2t<8>(af, w2a, lane, acc2);
        int r = m0 + (lane >> 2);
        #pragma unroll
        for (int nb = 0; nb < 16; nb++) {
            int c = nb * 8 + (lane & 3) * 2;
            int na = n0 + r, nb2 = n0 + r + 8;
            if constexpr (MODE == 0) {
                if (na < NN) *reinterpret_cast<float2*>(g_xn + (size_t)na * 128 + c) =
                    make_float2(acc2[nb][0], acc2[nb][1]);
                if (nb2 < NN) *reinterpret_cast<float2*>(g_xn + (size_t)nb2 * 128 + c) =
                    make_float2(acc2[nb][2], acc2[nb][3]);
            } else {
                *reinterpret_cast<float2*>(g_xe + (size_t)na * 128 + c) =
                    make_float2(acc2[nb][0], acc2[nb][1]);
                *reinterpret_cast<float2*>(g_xe + (size_t)nb2 * 128 + c) =
                    make_float2(acc2[nb][2], acc2[nb][3]);
            }
        }
        if constexpr (MODE == 0) {
            uint32_t af2[32];
            pack_id(acc2, af2);
            __syncthreads();
            cpWasync<NT>(aW, secN, t);       // Wa(l=0)
            cp_wait<0>(); __syncthreads();
            float acc3[16][4];
            #pragma unroll
            for (int i = 0; i < 16; i++) { acc3[i][0] = acc3[i][1] = acc3[i][2] = acc3[i][3] = 0.f; }
            gemm2t<8>(af2, aW, lane, acc3);
            store_y(g_ya, acc3, n0, m0, lane);
            __syncthreads();
            cpWasync<NT>(aW, secN + 1, t);   // Wb(l=0)
            cp_wait<0>(); __syncthreads();
            #pragma unroll
            for (int i = 0; i < 16; i++) { acc3[i][0] = acc3[i][1] = acc3[i][2] = acc3[i][3] = 0.f; }
            gemm2t<8>(af2, aW, lane, acc3);
            store_y(g_yb, acc3, n0, m0, lane);
        }
        return;
    } else {  // MODE 1: edge layer
        cpWasync<NT>(aW, sec0 + 2, t);   // Wxe
        const int e = n0 + ln;
        const float4* pe = (const float4*)(g_xe + (size_t)e * 128 + c0);
        #pragma unroll
        for (int u = 0; u < 8; u++) stX8(X0, ln, c0 + u * 8, pe[2 * u], pe[2 * u + 1]);
        const int r = m0 + (lane >> 2);
        const int eA = n0 + r, eB = n0 + r + 8;
        const int iA = iInd[eA], jA = jInd[eA], iB = iInd[eB], jB = jInd[eB];
        cp_wait<0>(); __syncthreads();
        gemmX<16, 8>(aX0, aW, m0, lane, acc);
        __syncthreads();
        cpWasync<NT>(aW, sec0 + 3, t);   // W2
        #pragma unroll
        for (int nb = 0; nb < 16; nb++) {
            int c = nb * 8 + (lane & 3) * 2;
            float2 a0 = *reinterpret_cast<const float2*>(g_ya + (size_t)iA * 128 + c);
            float2 b0 = *reinterpret_cast<const float2*>(g_yb + (size_t)jA * 128 + c);
            float2 a1 = *reinterpret_cast<const float2*>(g_ya + (size_t)iB * 128 + c);
            float2 b1 = *reinterpret_cast<const float2*>(g_yb + (size_t)jB * 128 + c);
            acc[nb][0] += a0.x + b0.x;
            acc[nb][1] += a0.y + b0.y;
            acc[nb][2] += a1.x + b1.x;
            acc[nb][3] += a1.y + b1.y;
        }
        uint32_t af[32];
        pack_tanh(acc, af);
        cp_wait<0>(); __syncthreads();
        float acc2[16][4];
        #pragma unroll
        for (int i = 0; i < 16; i++) { acc2[i][0] = acc2[i][1] = acc2[i][2] = acc2[i][3] = 0.f; }
        gemm2t<8>(af, aW, lane, acc2);
        #pragma unroll
        for (int nb = 0; nb < 16; nb++) {
            int c = nb * 8 + (lane & 3) * 2;
            float2 f0 = make_float2(acc2[nb][0], acc2[nb][1]);
            float2 f1 = make_float2(acc2[nb][2], acc2[nb][3]);
            g_fluxh[(size_t)eA * 64 + (c >> 1)] = h2pack(f0.x * FSCALE, f0.y * FSCALE);
            g_fluxh[(size_t)eB * 64 + (c >> 1)] = h2pack(f1.x * FSCALE, f1.y * FSCALE);
            float2 o0 = *reinterpret_cast<const float2*>(g_xe + (size_t)eA * 128 + c);
            float2 o1 = *reinterpret_cast<const float2*>(g_xe + (size_t)eB * 128 + c);
            float2 v0 = make_float2(o0.x - HSTEP * f0.x, o0.y - HSTEP * f0.y);
            float2 v1 = make_float2(o1.x - HSTEP * f1.x, o1.y - HSTEP * f1.y);
            if (dst) {
                dst[(size_t)c * NE + eA] = v0.x;
                dst[(size_t)(c + 1) * NE + eA] = v0.y;
                dst[(size_t)c * NE + eB] = v1.x;
                dst[(size_t)(c + 1) * NE + eB] = v1.y;
            } else {
                *reinterpret_cast<float2*>(g_xe + (size_t)eA * 128 + c) = v0;
                *reinterpret_cast<float2*>(g_xe + (size_t)eB * 128 + c) = v1;
            }
        }
        return;
    }
}

// Node layer with ALL W sections preloaded; MODE2 = +ya/yb(next), MODE5 = +close
template <int MODE>
__global__ void __launch_bounds__(128, 1)
node_layer(int sec0, int secN, float* __restrict__ dst) {
    constexpr int NT = 128;
    extern __shared__ char sm[];
    char* X0 = sm;                 // ave
    char* X1 = sm + 16384;         // div
    char* X2 = sm + 32768;         // xn
    const uint32_t sb = smem_u32(sm);
    const uint32_t aX0 = sb, aX1 = sb + 16384, aX2 = sb + 32768;
    const uint32_t aW0 = sb + 49152, aW1 = aW0 + 32768, aW2 = aW1 + 32768, aW3 = aW2 + 32768;

    const int t = threadIdx.x, lane = t & 31, w = t >> 5;
    const int n0 = blockIdx.x * 64;
    const int ln = t >> 1, cg = t & 1, c0 = cg * 64;
    const int m0 = w * 16;

    // preload all 4 node W sections (groups C1..C4)
    cpWasync<NT>(aW0, sec0, t);
    cpWasync<NT>(aW1, sec0 + 1, t);
    cpWasync<NT>(aW2, sec0 + 2, t);
    cpWasync<NT>(aW3, sec0 + 3, t);

    const int n = n0 + ln;
    const int ns = (n < NN) ? n : 0;
    {
        const uint4* pa = (const uint4*)(g_aveh + (size_t)ns * 64 + (c0 >> 1));
        const uint4* pd = (const uint4*)(g_divh + (size_t)ns * 64 + (c0 >> 1));
        #pragma unroll
        for (int u = 0; u < 8; u++) {
            *reinterpret_cast<uint4*>(X0 + toff(ln, c0 + u * 8)) = pa[u];
            *reinterpret_cast<uint4*>(X1 + toff(ln, c0 + u * 8)) = pd[u];
        }
        const float4* p = (const float4*)(g_xn + (size_t)ns * 128 + c0);
        #pragma unroll
        for (int u = 0; u < 8; u++) stX8(X2, ln, c0 + u * 8, p[2 * u], p[2 * u + 1]);
    }
    float acc[16][4];
    #pragma unroll
    for (int i = 0; i < 16; i++) { acc[i][0] = acc[i][1] = acc[i][2] = acc[i][3] = 0.f; }

    cp_wait<3>(); __syncthreads();                 // C1 (W0) done
    gemmX<16, 8>(aX0, aW0, m0, lane, acc);         // aveE
    __syncthreads();
    cpWasync<NT>(aW0, secN, t);                    // C5: ya-W (MODE2) / close-W (MODE5)
    cp_wait<3>(); __syncthreads();                 // C2 (W1) done
    gemmX<16, 8>(aX1, aW1, m0, lane, acc);         // divE
    if constexpr (MODE == 2) {
        __syncthreads();
        cpWasync<NT>(aW1, secN + 1, t);            // C6: yb-W
        cp_wait<3>(); __syncthreads();             // C3 (W2) done
    } else {
        cp_wait<2>(); __syncthreads();             // C3 done (pending C4,C5)
    }
    gemmX<16, 8>(aX2, aW2, m0, lane, acc);         // xn
    if constexpr (MODE == 2) { cp_wait<2>(); } else { cp_wait<1>(); }   // C4 (W3) done
    __syncthreads();
    uint32_t af[32];
    pack_tanh(acc, af);
    float acc2[16][4];
    #pragma unroll
    for (int i = 0; i < 16; i++) { acc2[i][0] = acc2[i][1] = acc2[i][2] = acc2[i][3] = 0.f; }
    gemm2t<8>(af, aW3, lane, acc2);

    // xn_new in registers; write to gmem
    int r = m0 + (lane >> 2);
    int na = n0 + r, nb2 = n0 + r + 8;
    int naC = (na < NN) ? na : 0, nbC = (nb2 < NN) ? nb2 : 0;
    #pragma unroll
    for (int nb = 0; nb < 16; nb++) {
        int c = nb * 8 + (lane & 3) * 2;
        float2 o0 = *reinterpret_cast<const float2*>(g_xn + (size_t)naC * 128 + c);
        float2 o1 = *reinterpret_cast<const float2*>(g_xn + (size_t)nbC * 128 + c);
        acc2[nb][0] = o0.x - HSTEP * acc2[nb][0];
        acc2[nb][1] = o0.y - HSTEP * acc2[nb][1];
        acc2[nb][2] = o1.x - HSTEP * acc2[nb][2];
        acc2[nb][3] = o1.y - HSTEP * acc2[nb][3];
        if (na < NN) *reinterpret_cast<float2*>(g_xn + (size_t)na * 128 + c) =
            make_float2(acc2[nb][0], acc2[nb][1]);
        if (nb2 < NN) *reinterpret_cast<float2*>(g_xn + (size_t)nb2 * 128 + c) =
            make_float2(acc2[nb][2], acc2[nb][3]);
    }
    uint32_t af2[32];
    pack_id(acc2, af2);
    if constexpr (MODE == 2) {
        cp_wait<1>(); __syncthreads();             // C5 (ya-W in slot0) done
        float acc3[16][4];
        #pragma unroll
        for (int i = 0; i < 16; i++) { acc3[i][0] = acc3[i][1] = acc3[i][2] = acc3[i][3] = 0.f; }
        gemm2t<8>(af2, aW0, lane, acc3);
        store_y(g_ya, acc3, n0, m0, lane);
        cp_wait<0>(); __syncthreads();             // C6 (yb-W in slot1) done
        #pragma unroll
        for (int i = 0; i < 16; i++) { acc3[i][0] = acc3[i][1] = acc3[i][2] = acc3[i][3] = 0.f; }
        gemm2t<8>(af2, aW1, lane, acc3);
        store_y(g_yb, acc3, n0, m0, lane);
    } else {
        cp_wait<0>(); __syncthreads();             // C5 (close-W in slot0) done
        float acc3[8][4];
        #pragma unroll
        for (int i = 0; i < 8; i++) { acc3[i][0] = acc3[i][1] = acc3[i][2] = acc3[i][3] = 0.f; }
        gemm2t<4>(af2, aW0, lane, acc3);
        #pragma unroll
        for (int nb = 0; nb < 8; nb++) {
            int c = nb * 8 + (lane & 3) * 2;
            if (na < NN) {
                dst[(size_t)c * NN + na] = acc3[nb][0];
                dst[(size_t)(c + 1) * NN + na] = acc3[nb][1];
            }
            if (nb2 < NN) {
                dst[(size_t)c * NN + nb2] = acc3[nb][2];
                dst[(size_t)(c + 1) * NN + nb2] = acc3[nb][3];
            }
        }
    }
}

extern "C" void kernel_launch(void* const* d_in, const int* in_sizes, int n_in,
                              void* d_out, int out_size) {
    const float* xn_in = (const float*)d_in[0];
    const float* xe_in = (const float*)d_in[1];
    const int*   iInd  = (const int*)d_in[2];
    const int*   jInd  = (const int*)d_in[3];
    int wi = (n_in >= 14) ? 5 : 4;
    const float* K1Nopen = (const float*)d_in[wi + 0];
    const float* K2Nopen = (const float*)d_in[wi + 1];
    const float* K1Eopen = (const float*)d_in[wi + 2];
    const float* K2Eopen = (const float*)d_in[wi + 3];
    const float* KNclose = (const float*)d_in[wi + 4];
    const float* KE1     = (const float*)d_in[wi + 5];
    const float* KE2     = (const float*)d_in[wi + 6];
    const float* KN1     = (const float*)d_in[wi + 7];
    const float* KN2     = (const float*)d_in[wi + 8];
    float* out = (float*)d_out;

    const int smOpenE = 49152;   // X0 + W
    const int smOpenN = 81920;   // X0 + W0 + W1
    const int smEdge  = 49152;   // X0 + W
    const int smNode  = 180224;  // X0,X1,X2 (48K) + 4x W (128K)

    cudaFuncSetAttribute(mm2_layer<0>, cudaFuncAttributeMaxDynamicSharedMemorySize, smOpenN);
    cudaFuncSetAttribute(mm2_layer<4>, cudaFuncAttributeMaxDynamicSharedMemorySize, smOpenE);
    cudaFuncSetAttribute(mm2_layer<1>, cudaFuncAttributeMaxDynamicSharedMemorySize, smEdge);
    cudaFuncSetAttribute(node_layer<2>, cudaFuncAttributeMaxDynamicSharedMemorySize, smNode);
    cudaFuncSetAttribute(node_layer<5>, cudaFuncAttributeMaxDynamicSharedMemorySize, smNode);

    const int gN64 = (NN + 63) / 64;   // 157
    const int gE64 = NE / 64;          // 2500

    // Keep mm2_layer<4> at launch index 3 for the ncu capture slot.
    k_pack<<<37, 256>>>(KE1, KE2, KN1, KN2, K1Nopen, K2Nopen, K1Eopen, K2Eopen, KNclose);
    k_zero_cursor<<<(NN + 255) / 256, 256>>>();
    k_deg<<<(NE + 255) / 256, 256>>>(iInd, jInd);
    mm2_layer<4><<<gE64, 128, smOpenE>>>(34, 0, xe_in, nullptr, nullptr, nullptr, NE);
    k_scan<<<1, 1024>>>();
    k_fill<<<(NE + 255) / 256, 256>>>(iInd, jInd);
    mm2_layer<0><<<gN64, 128, smOpenN>>>(32, 0, xn_in, nullptr, nullptr, nullptr, NN);

    for (int l = 0; l < 4; l++) {
        float* edst = (l == 3) ? (out + (size_t)64 * NN) : nullptr;
        mm2_layer<1><<<gE64, 128, smEdge>>>(l * 4, 0, nullptr, edst, iInd, jInd, NE);
        k_gather<<<(NN + 31) / 32, 256>>>();
        if (l < 3)
            node_layer<2><<<gN64, 128, smNode>>>(16 + l * 4, (l + 1) * 4, nullptr);
        else
            node_layer<5><<<gN64, 128, smNode>>>(16 + l * 4, 36, out);
    }
}

// round 15
// speedup vs baseline: 1.0330x; 1.0330x over previous
#include <cuda_runtime.h>
#include <cuda_fp16.h>
#include <cstdint>

constexpr int NN = 10000;
constexpr int NE = 160000;
constexpr float HSTEP = 0.1f;
constexpr float FSCALE = 256.0f;
constexpr float FINV = 1.0f / 256.0f;

__device__ float g_xn[NN * 128];
__device__ float g_xe[(size_t)NE * 128];
__device__ float g_ya[NN * 128];
__device__ float g_yb[NN * 128];
__device__ uint32_t g_fluxh[(size_t)NE * 64];
__device__ uint32_t g_aveh[NN * 64];
__device__ uint32_t g_divh[NN * 64];
__device__ int g_rowptr[NN + 1];
__device__ int g_cursor[NN];
__device__ int g_elist[2 * NE];
__device__ uint8_t g_wpack[37 * 32768];

// ---------------- CSR build ----------------
__global__ void k_deg(const int* __restrict__ iInd, const int* __restrict__ jInd) {
    int e = blockIdx.x * blockDim.x + threadIdx.x;
    if (e < NE) { atomicAdd(&g_cursor[iInd[e]], 1); atomicAdd(&g_cursor[jInd[e]], 1); }
}
__global__ void k_scan() {
    __shared__ int part[1024];
    const int t = threadIdx.x;
    constexpr int CH = (NN + 1023) / 1024;
    int base = t * CH, loc[CH], s = 0;
    #pragma unroll
    for (int k = 0; k < CH; k++) {
        int idx = base + k;
        int v = (idx < NN) ? g_cursor[idx] : 0;
        loc[k] = s; s += v;
    }
    part[t] = s;
    __syncthreads();
    for (int off = 1; off < 1024; off <<= 1) {
        int v = 0;
        if (t >= off) v = part[t - off];
        __syncthreads();
        if (t >= off) part[t] += v;
        __syncthreads();
    }
    int pre = (t == 0) ? 0 : part[t - 1];
    #pragma unroll
    for (int k = 0; k < CH; k++) {
        int idx = base + k;
        if (idx < NN) { int rp = pre + loc[k]; g_rowptr[idx] = rp; g_cursor[idx] = rp; }
    }
    if (t == 1023) g_rowptr[NN] = part[1023];
}
__global__ void k_fill(const int* __restrict__ iInd, const int* __restrict__ jInd) {
    int e = blockIdx.x * blockDim.x + threadIdx.x;
    if (e < NE) {
        int p = atomicAdd(&g_cursor[iInd[e]], 1); g_elist[p] = 2 * e;
        int q = atomicAdd(&g_cursor[jInd[e]], 1); g_elist[q] = 2 * e + 1;
    }
}

// ---------------- helpers ----------------
__device__ __forceinline__ uint32_t smem_u32(const void* p) {
    uint32_t a;
    asm("{ .reg .u64 t; cvta.to.shared.u64 t, %1; cvt.u32.u64 %0, t; }" : "=r"(a) : "l"(p));
    return a;
}
__host__ __device__ __forceinline__ uint32_t toff(int row, int k) {
    return (uint32_t)(row * 256) + (uint32_t)((((((k >> 3)) ^ row) & 15) << 4) | ((k & 7) * 2));
}
__device__ __forceinline__ uint32_t h2pack(float a, float b) {
    __half2 hh = __floats2half2_rn(a, b);
    return *reinterpret_cast<uint32_t*>(&hh);
}
__device__ __forceinline__ float2 h2unpack(uint32_t v) {
    return __half22float2(*reinterpret_cast<__half2*>(&v));
}
__device__ __forceinline__ void stX8(char* buf, int row, int k, float4 a, float4 b) {
    *reinterpret_cast<uint4*>(buf + toff(row, k)) =
        make_uint4(h2pack(a.x, a.y), h2pack(a.z, a.w), h2pack(b.x, b.y), h2pack(b.z, b.w));
}
__device__ __forceinline__ void ldmx4(uint32_t* r, uint32_t a) {
    asm volatile("ldmatrix.sync.aligned.m8n8.x4.shared.b16 {%0,%1,%2,%3}, [%4];"
                 : "=r"(r[0]), "=r"(r[1]), "=r"(r[2]), "=r"(r[3]) : "r"(a));
}
__device__ __forceinline__ void mma16816(float* d, const uint32_t* a, uint32_t b0, uint32_t b1) {
    asm volatile(
        "mma.sync.aligned.m16n8k16.row.col.f32.f16.f16.f32 "
        "{%0,%1,%2,%3},{%4,%5,%6,%7},{%8,%9},{%0,%1,%2,%3};"
        : "+f"(d[0]), "+f"(d[1]), "+f"(d[2]), "+f"(d[3])
        : "r"(a[0]), "r"(a[1]), "r"(a[2]), "r"(a[3]), "r"(b0), "r"(b1));
}
template <int NT>
__device__ __forceinline__ void cpWasync(uint32_t wsm, int sec, int t) {
    const char* src = reinterpret_cast<const char*>(g_wpack) + (size_t)sec * 32768 + t * 16;
    uint32_t dst = wsm + t * 16;
    #pragma unroll
    for (int i = 0; i < 2048 / NT; i++)
        asm volatile("cp.async.cg.shared.global [%0], [%1], 16;"
                     :: "r"(dst + i * NT * 16), "l"(src + i * NT * 16) : "memory");
    asm volatile("cp.async.commit_group;" ::: "memory");
}
template <int N>
__device__ __forceinline__ void cp_wait() {
    asm volatile("cp.async.wait_group %0;" :: "n"(N) : "memory");
}

template <int NBLK, int KS>
__device__ __forceinline__ void gemmX(uint32_t xa, uint32_t wa, int m0, int lane, float acc[][4]) {
    #pragma unroll
    for (int ks = 0; ks < KS; ks++) {
        int k0 = ks * 16;
        uint32_t ah[4];
        ldmx4(ah, xa + toff(m0 + (lane & 15), k0 + ((lane >> 4) << 3)));
        #pragma unroll
        for (int p = 0; p < NBLK / 2; p++) {
            uint32_t bh[4];
            ldmx4(bh, wa + toff(p * 16 + (lane & 7) + ((lane >> 4) << 3),
                                k0 + (((lane >> 3) & 1) << 3)));
            mma16816(acc[2 * p],     ah, bh[0], bh[1]);
            mma16816(acc[2 * p + 1], ah, bh[2], bh[3]);
        }
    }
}
__device__ __forceinline__ void pack_tanh(const float acc[][4], uint32_t* af) {
    #pragma unroll
    for (int ks = 0; ks < 8; ks++) {
        af[4 * ks + 0] = h2pack(tanhf(acc[2 * ks][0]),     tanhf(acc[2 * ks][1]));
        af[4 * ks + 1] = h2pack(tanhf(acc[2 * ks][2]),     tanhf(acc[2 * ks][3]));
        af[4 * ks + 2] = h2pack(tanhf(acc[2 * ks + 1][0]), tanhf(acc[2 * ks + 1][1]));
        af[4 * ks + 3] = h2pack(tanhf(acc[2 * ks + 1][2]), tanhf(acc[2 * ks + 1][3]));
    }
}
__device__ __forceinline__ void pack_id(const float acc[][4], uint32_t* af) {
    #pragma unroll
    for (int ks = 0; ks < 8; ks++) {
        af[4 * ks + 0] = h2pack(acc[2 * ks][0],     acc[2 * ks][1]);
        af[4 * ks + 1] = h2pack(acc[2 * ks][2],     acc[2 * ks][3]);
        af[4 * ks + 2] = h2pack(acc[2 * ks + 1][0], acc[2 * ks + 1][1]);
        af[4 * ks + 3] = h2pack(acc[2 * ks + 1][2], acc[2 * ks + 1][3]);
    }
}
template <int NP>
__device__ __forceinline__ void gemm2t(const uint32_t* af, uint32_t wa, int lane, float acc2[][4]) {
    #pragma unroll
    for (int ks = 0; ks < 8; ks++) {
        int k0 = ks * 16;
        #pragma unroll
        for (int p = 0; p < NP; p++) {
            uint32_t bh[4];
            ldmx4(bh, wa + toff(p * 16 + (lane & 7) + ((lane >> 4) << 3),
                                k0 + (((lane >> 3) & 1) << 3)));
            mma16816(acc2[2 * p],     af + 4 * ks, bh[0], bh[1]);
            mma16816(acc2[2 * p + 1], af + 4 * ks, bh[2], bh[3]);
        }
    }
}
__device__ __forceinline__ void store_y(float* dstbuf, const float acc[][4],
                                        int n0, int m0, int lane) {
    int r = m0 + (lane >> 2);
    int na = n0 + r, nb2 = n0 + r + 8;
    #pragma unroll
    for (int nb = 0; nb < 16; nb++) {
        int c = nb * 8 + (lane & 3) * 2;
        if (na < NN)  *reinterpret_cast<float2*>(dstbuf + (size_t)na * 128 + c) =
            make_float2(acc[nb][0], acc[nb][1]);
        if (nb2 < NN) *reinterpret_cast<float2*>(dstbuf + (size_t)nb2 * 128 + c) =
            make_float2(acc[nb][2], acc[nb][3]);
    }
}

// ---------------- flux -> dense ave/div ----------------
__device__ __forceinline__ void acc_edge(int v, int p0, float2* s, float2* d) {
    int e = v >> 1;
    float sg = (v & 1) ? -1.f : 1.f;
    const uint4* f4 = (const uint4*)(g_fluxh + (size_t)e * 64 + p0);
    uint4 a = f4[0], b = f4[1];
    uint32_t wds[8] = {a.x, a.y, a.z, a.w, b.x, b.y, b.z, b.w};
    #pragma unroll
    for (int q = 0; q < 8; q++) {
        float2 f = h2unpack(wds[q]);
        s[q].x += f.x; s[q].y += f.y;
        d[q].x = fmaf(sg, f.x, d[q].x);
        d[q].y = fmaf(sg, f.y, d[q].y);
    }
}
__global__ void __launch_bounds__(256) k_gather() {
    int t = threadIdx.x;
    int node = blockIdx.x * 32 + (t >> 3);
    int p0 = (t & 7) * 8;
    if (node >= NN) return;
    float2 s[8], d[8];
    #pragma unroll
    for (int q = 0; q < 8; q++) { s[q] = make_float2(0.f, 0.f); d[q] = make_float2(0.f, 0.f); }
    int beg = g_rowptr[node], end = g_rowptr[node + 1];
    int p = beg;
    for (; p + 4 <= end; p += 4) {
        int v0 = g_elist[p], v1 = g_elist[p + 1], v2 = g_elist[p + 2], v3 = g_elist[p + 3];
        acc_edge(v0, p0, s, d);
        acc_edge(v1, p0, s, d);
        acc_edge(v2, p0, s, d);
        acc_edge(v3, p0, s, d);
    }
    for (; p < end; p++) acc_edge(g_elist[p], p0, s, d);
    uint32_t oa[8], od[8];
    #pragma unroll
    for (int q = 0; q < 8; q++) {
        oa[q] = h2pack(s[q].x * (0.5f * FINV), s[q].y * (0.5f * FINV));
        od[q] = h2pack(d[q].x * FINV, d[q].y * FINV);
    }
    uint4* pa = (uint4*)(g_aveh + (size_t)node * 64 + p0);
    uint4* pd = (uint4*)(g_divh + (size_t)node * 64 + p0);
    pa[0] = make_uint4(oa[0], oa[1], oa[2], oa[3]);
    pa[1] = make_uint4(oa[4], oa[5], oa[6], oa[7]);
    pd[0] = make_uint4(od[0], od[1], od[2], od[3]);
    pd[1] = make_uint4(od[4], od[5], od[6], od[7]);
}

// ---------------- weight pre-pack (also zeros CSR cursor) ----------------
__global__ void k_pack(const float* __restrict__ KE1, const float* __restrict__ KE2,
                       const float* __restrict__ KN1, const float* __restrict__ KN2,
                       const float* __restrict__ K1N, const float* __restrict__ K2N,
                       const float* __restrict__ K1E, const float* __restrict__ K2E,
                       const float* __restrict__ KNc) {
    int sec = blockIdx.x;
    for (int i = sec * 256 + threadIdx.x; i < NN; i += 37 * 256) g_cursor[i] = 0;
    uint8_t* dst = g_wpack + (size_t)sec * 32768;
    for (int v = threadIdx.x; v < 16384; v += 256) {
        int o = v >> 7, c = v & 127;
        float val = 0.f;
        if (sec < 16) {
            int l = sec >> 2, kd = sec & 3;
            const float* E1 = KE1 + (size_t)l * 128 * 384;
            if (kd == 0)      val = 0.5f * E1[o * 384 + c] + E1[o * 384 + 256 + c];
            else if (kd == 1) val = 0.5f * E1[o * 384 + c] - E1[o * 384 + 256 + c];
            else if (kd == 2) val = E1[o * 384 + 128 + c];
            else              val = KE2[(size_t)l * 16384 + o * 128 + c];
        } else if (sec < 32) {
            int l = (sec - 16) >> 2, kd = sec & 3;
            const float* N1 = KN1 + (size_t)l * 128 * 384;
            if (kd == 0)      val = N1[o * 384 + c];
            else if (kd == 1) val = N1[o * 384 + 128 + c];
            else if (kd == 2) val = N1[o * 384 + 256 + c];
            else              val = KN2[(size_t)l * 16384 + o * 128 + c];
        } else if (sec == 32) { val = (c < 64) ? K1N[o * 64 + c] : 0.f; }
        else if (sec == 33)   { val = K2N[o * 128 + c]; }
        else if (sec == 34)   { val = (c < 64) ? K1E[o * 64 + c] : 0.f; }
        else if (sec == 35)   { val = K2E[o * 128 + c]; }
        else                  { val = (o < 64) ? KNc[o * 128 + c] : 0.f; }
        *reinterpret_cast<__half*>(dst + toff(o, c)) = __float2half(val);
    }
}

// MODE: 0 openN (+ya/yb l0), 4 openE, 1 edge
template <int MODE>
__global__ void __launch_bounds__(128, (MODE == 4 || MODE == 1) ? 4 : 2)
mm2_layer(int sec0, int secN, const float* __restrict__ src, float* __restrict__ dst,
          const int* __restrict__ iInd, const int* __restrict__ jInd, int ncols) {
    constexpr int MT = 64;
    constexpr int NT = 128;
    constexpr uint32_t XB = 16384;
    extern __shared__ char sm[];
    char* X0 = sm;
    const uint32_t sb = smem_u32(sm);
    const uint32_t aX0 = sb;
    const uint32_t aW  = sb + XB;
    const uint32_t aW1 = aW + 32768u;

    const int t = threadIdx.x, lane = t & 31, w = t >> 5;
    const int n0 = blockIdx.x * MT;
    const int ln = t >> 1, cg = t & 1, c0 = cg * 64;
    const int m0 = w * 16;

    float acc[16][4];
    #pragma unroll
    for (int i = 0; i < 16; i++) { acc[i][0] = acc[i][1] = acc[i][2] = acc[i][3] = 0.f; }

    if constexpr (MODE == 0 || MODE == 4) {
        cpWasync<NT>(aW, sec0, t);
        if (MODE == 0) cpWasync<NT>(aW1, sec0 + 1, t);
        int n = n0 + ln;
        bool valid = (MODE == 4) || (n < ncols);
        int ns = valid ? n : 0;
        int kb = cg * 32;
        #pragma unroll
        for (int u = 0; u < 4; u++) {
            float4 a = make_float4(0.f, 0.f, 0.f, 0.f), b = a;
            if (valid) {
                int c = kb + u * 8;
                a.x = src[(size_t)(c + 0) * ncols + ns]; a.y = src[(size_t)(c + 1) * ncols + ns];
                a.z = src[(size_t)(c + 2) * ncols + ns]; a.w = src[(size_t)(c + 3) * ncols + ns];
                b.x = src[(size_t)(c + 4) * ncols + ns]; b.y = src[(size_t)(c + 5) * ncols + ns];
                b.z = src[(size_t)(c + 6) * ncols + ns]; b.w = src[(size_t)(c + 7) * ncols + ns];
            }
            stX8(X0, ln, kb + u * 8, a, b);
        }
        cp_wait<0>(); __syncthreads();
        gemmX<16, 4>(aX0, aW, m0, lane, acc);
        uint32_t af[32];
        pack_tanh(acc, af);
        uint32_t w2a = aW;
        if (MODE == 0) {
            w2a = aW1;
        } else {
            __syncthreads();
            cpWasync<NT>(aW, sec0 + 1, t);
            cp_wait<0>(); __syncthreads();
        }
        float acc2[16][4];
        #pragma unroll
        for (int i = 0; i < 16; i++) { acc2[i][0] = acc2[i][1] = acc2[i][2] = acc2[i][3] = 0.f; }
        gemm2t<8>(af, w2a, lane, acc2);
        int r = m0 + (lane >> 2);
        #pragma unroll
        for (int nb = 0; nb < 16; nb++) {
            int c = nb * 8 + (lane & 3) * 2;
            int na = n0 + r, nb2 = n0 + r + 8;
            if constexpr (MODE == 0) {
                if (na < NN) *reinterpret_cast<float2*>(g_xn + (size_t)na * 128 + c) =
                    make_float2(acc2[nb][0], acc2[nb][1]);
                if (nb2 < NN) *reinterpret_cast<float2*>(g_xn + (size_t)nb2 * 128 + c) =
                    make_float2(acc2[nb][2], acc2[nb][3]);
            } else {
                *reinterpret_cast<float2*>(g_xe + (size_t)na * 128 + c) =
                    make_float2(acc2[nb][0], acc2[nb][1]);
                *reinterpret_cast<float2*>(g_xe + (size_t)nb2 * 128 + c) =
                    make_float2(acc2[nb][2], acc2[nb][3]);
            }
        }
        if constexpr (MODE == 0) {
            uint32_t af2[32];
            pack_id(acc2, af2);
            __syncthreads();
            cpWasync<NT>(aW, secN, t);
            cp_wait<0>(); __syncthreads();
            float acc3[16][4];
            #pragma unroll
            for (int i = 0; i < 16; i++) { acc3[i][0] = acc3[i][1] = acc3[i][2] = acc3[i][3] = 0.f; }
            gemm2t<8>(af2, aW, lane, acc3);
            store_y(g_ya, acc3, n0, m0, lane);
            __syncthreads();
            cpWasync<NT>(aW, secN + 1, t);
            cp_wait<0>(); __syncthreads();
            #pragma unroll
            for (int i = 0; i < 16; i++) { acc3[i][0] = acc3[i][1] = acc3[i][2] = acc3[i][3] = 0.f; }
            gemm2t<8>(af2, aW, lane, acc3);
            store_y(g_yb, acc3, n0, m0, lane);
        }
        return;
    } else {  // MODE 1: edge layer
        cpWasync<NT>(aW, sec0 + 2, t);
        const int e = n0 + ln;
        const float4* pe = (const float4*)(g_xe + (size_t)e * 128 + c0);
        #pragma unroll
        for (int u = 0; u < 8; u++) stX8(X0, ln, c0 + u * 8, pe[2 * u], pe[2 * u + 1]);
        const int r = m0 + (lane >> 2);
        const int eA = n0 + r, eB = n0 + r + 8;
        const int iA = iInd[eA], jA = jInd[eA], iB = iInd[eB], jB = jInd[eB];
        cp_wait<0>(); __syncthreads();
        gemmX<16, 8>(aX0, aW, m0, lane, acc);
        __syncthreads();
        cpWasync<NT>(aW, sec0 + 3, t);
        #pragma unroll
        for (int nb = 0; nb < 16; nb++) {
            int c = nb * 8 + (lane & 3) * 2;
            float2 a0 = *reinterpret_cast<const float2*>(g_ya + (size_t)iA * 128 + c);
            float2 b0 = *reinterpret_cast<const float2*>(g_yb + (size_t)jA * 128 + c);
            float2 a1 = *reinterpret_cast<const float2*>(g_ya + (size_t)iB * 128 + c);
            float2 b1 = *reinterpret_cast<const float2*>(g_yb + (size_t)jB * 128 + c);
            acc[nb][0] += a0.x + b0.x;
            acc[nb][1] += a0.y + b0.y;
            acc[nb][2] += a1.x + b1.x;
            acc[nb][3] += a1.y + b1.y;
        }
        uint32_t af[32];
        pack_tanh(acc, af);
        cp_wait<0>(); __syncthreads();
        float acc2[16][4];
        #pragma unroll
        for (int i = 0; i < 16; i++) { acc2[i][0] = acc2[i][1] = acc2[i][2] = acc2[i][3] = 0.f; }
        gemm2t<8>(af, aW, lane, acc2);
        #pragma unroll
        for (int nb = 0; nb < 16; nb++) {
            int c = nb * 8 + (lane & 3) * 2;
            float2 f0 = make_float2(acc2[nb][0], acc2[nb][1]);
            float2 f1 = make_float2(acc2[nb][2], acc2[nb][3]);
            g_fluxh[(size_t)eA * 64 + (c >> 1)] = h2pack(f0.x * FSCALE, f0.y * FSCALE);
            g_fluxh[(size_t)eB * 64 + (c >> 1)] = h2pack(f1.x * FSCALE, f1.y * FSCALE);
            float2 o0 = *reinterpret_cast<const float2*>(g_xe + (size_t)eA * 128 + c);
            float2 o1 = *reinterpret_cast<const float2*>(g_xe + (size_t)eB * 128 + c);
            float2 v0 = make_float2(o0.x - HSTEP * f0.x, o0.y - HSTEP * f0.y);
            float2 v1 = make_float2(o1.x - HSTEP * f1.x, o1.y - HSTEP * f1.y);
            if (dst) {
                dst[(size_t)c * NE + eA] = v0.x;
                dst[(size_t)(c + 1) * NE + eA] = v0.y;
                dst[(size_t)c * NE + eB] = v1.x;
                dst[(size_t)(c + 1) * NE + eB] = v1.y;
            } else {
                *reinterpret_cast<float2*>(g_xe + (size_t)eA * 128 + c) = v0;
                *reinterpret_cast<float2*>(g_xe + (size_t)eB * 128 + c) = v1;
            }
        }
        return;
    }
}

// Node layer, all W preloaded; MODE2 = +ya/yb(next), MODE5 = +close
template <int MODE>
__global__ void __launch_bounds__(128, 1)
node_layer(int sec0, int secN, float* __restrict__ dst) {
    constexpr int NT = 128;
    extern __shared__ char sm[];
    char* X0 = sm;
    char* X1 = sm + 16384;
    char* X2 = sm + 32768;
    const uint32_t sb = smem_u32(sm);
    const uint32_t aX0 = sb, aX1 = sb + 16384, aX2 = sb + 32768;
    const uint32_t aW0 = sb + 49152, aW1 = aW0 + 32768, aW2 = aW1 + 32768, aW3 = aW2 + 32768;

    const int t = threadIdx.x, lane = t & 31, w = t >> 5;
    const int n0 = blockIdx.x * 64;
    const int ln = t >> 1, cg = t & 1, c0 = cg * 64;
    const int m0 = w * 16;

    cpWasync<NT>(aW0, sec0, t);
    cpWasync<NT>(aW1, sec0 + 1, t);
    cpWasync<NT>(aW2, sec0 + 2, t);
    cpWasync<NT>(aW3, sec0 + 3, t);

    const int n = n0 + ln;
    const int ns = (n < NN) ? n : 0;
    {
        const uint4* pa = (const uint4*)(g_aveh + (size_t)ns * 64 + (c0 >> 1));
        const uint4* pd = (const uint4*)(g_divh + (size_t)ns * 64 + (c0 >> 1));
        #pragma unroll
        for (int u = 0; u < 8; u++) {
            *reinterpret_cast<uint4*>(X0 + toff(ln, c0 + u * 8)) = pa[u];
            *reinterpret_cast<uint4*>(X1 + toff(ln, c0 + u * 8)) = pd[u];
        }
        const float4* p = (const float4*)(g_xn + (size_t)ns * 128 + c0);
        #pragma unroll
        for (int u = 0; u < 8; u++) stX8(X2, ln, c0 + u * 8, p[2 * u], p[2 * u + 1]);
    }
    float acc[16][4];
    #pragma unroll
    for (int i = 0; i < 16; i++) { acc[i][0] = acc[i][1] = acc[i][2] = acc[i][3] = 0.f; }

    cp_wait<3>(); __syncthreads();
    gemmX<16, 8>(aX0, aW0, m0, lane, acc);
    __syncthreads();
    cpWasync<NT>(aW0, secN, t);
    cp_wait<3>(); __syncthreads();
    gemmX<16, 8>(aX1, aW1, m0, lane, acc);
    if constexpr (MODE == 2) {
        __syncthreads();
        cpWasync<NT>(aW1, secN + 1, t);
        cp_wait<3>(); __syncthreads();
    } else {
        cp_wait<2>(); __syncthreads();
    }
    gemmX<16, 8>(aX2, aW2, m0, lane, acc);
    if constexpr (MODE == 2) { cp_wait<2>(); } else { cp_wait<1>(); }
    __syncthreads();
    uint32_t af[32];
    pack_tanh(acc, af);
    float acc2[16][4];
    #pragma unroll
    for (int i = 0; i < 16; i++) { acc2[i][0] = acc2[i][1] = acc2[i][2] = acc2[i][3] = 0.f; }
    gemm2t<8>(af, aW3, lane, acc2);

    int r = m0 + (lane >> 2);
    int na = n0 + r, nb2 = n0 + r + 8;
    int naC = (na < NN) ? na : 0, nbC = (nb2 < NN) ? nb2 : 0;
    #pragma unroll
    for (int nb = 0; nb < 16; nb++) {
        int c = nb * 8 + (lane & 3) * 2;
        float2 o0 = *reinterpret_cast<const float2*>(g_xn + (size_t)naC * 128 + c);
        float2 o1 = *reinterpret_cast<const float2*>(g_xn + (size_t)nbC * 128 + c);
        acc2[nb][0] = o0.x - HSTEP * acc2[nb][0];
        acc2[nb][1] = o0.y - HSTEP * acc2[nb][1];
        acc2[nb][2] = o1.x - HSTEP * acc2[nb][2];
        acc2[nb][3] = o1.y - HSTEP * acc2[nb][3];
        if (na < NN) *reinterpret_cast<float2*>(g_xn + (size_t)na * 128 + c) =
            make_float2(acc2[nb][0], acc2[nb][1]);
        if (nb2 < NN) *reinterpret_cast<float2*>(g_xn + (size_t)nb2 * 128 + c) =
            make_float2(acc2[nb][2], acc2[nb][3]);
    }
    uint32_t af2[32];
    pack_id(acc2, af2);
    if constexpr (MODE == 2) {
        cp_wait<1>(); __syncthreads();
        float acc3[16][4];
        #pragma unroll
        for (int i = 0; i < 16; i++) { acc3[i][0] = acc3[i][1] = acc3[i][2] = acc3[i][3] = 0.f; }
        gemm2t<8>(af2, aW0, lane, acc3);
        store_y(g_ya, acc3, n0, m0, lane);
        cp_wait<0>(); __syncthreads();
        #pragma unroll
        for (int i = 0; i < 16; i++) { acc3[i][0] = acc3[i][1] = acc3[i][2] = acc3[i][3] = 0.f; }
        gemm2t<8>(af2, aW1, lane, acc3);
        store_y(g_yb, acc3, n0, m0, lane);
    } else {
        cp_wait<0>(); __syncthreads();
        float acc3[8][4];
        #pragma unroll
        for (int i = 0; i < 8; i++) { acc3[i][0] = acc3[i][1] = acc3[i][2] = acc3[i][3] = 0.f; }
        gemm2t<4>(af2, aW0, lane, acc3);
        #pragma unroll
        for (int nb = 0; nb < 8; nb++) {
            int c = nb * 8 + (lane & 3) * 2;
            if (na < NN) {
                dst[(size_t)c * NN + na] = acc3[nb][0];
                dst[(size_t)(c + 1) * NN + na] = acc3[nb][1];
            }
            if (nb2 < NN) {
                dst[(size_t)c * NN + nb2] = acc3[nb][2];
                dst[(size_t)(c + 1) * NN + nb2] = acc3[nb][3];
            }
        }
    }
}

extern "C" void kernel_launch(void* const* d_in, const int* in_sizes, int n_in,
                              void* d_out, int out_size) {
    const float* xn_in = (const float*)d_in[0];
    const float* xe_in = (const float*)d_in[1];
    const int*   iInd  = (const int*)d_in[2];
    const int*   jInd  = (const int*)d_in[3];
    int wi = (n_in >= 14) ? 5 : 4;
    const float* K1Nopen = (const float*)d_in[wi + 0];
    const float* K2Nopen = (const float*)d_in[wi + 1];
    const float* K1Eopen = (const float*)d_in[wi + 2];
    const float* K2Eopen = (const float*)d_in[wi + 3];
    const float* KNclose = (const float*)d_in[wi + 4];
    const float* KE1     = (const float*)d_in[wi + 5];
    const float* KE2     = (const float*)d_in[wi + 6];
    const float* KN1     = (const float*)d_in[wi + 7];
    const float* KN2     = (const float*)d_in[wi + 8];
    float* out = (float*)d_out;

    const int smOpenE = 49152;
    const int smOpenN = 81920;
    const int smEdge  = 49152;
    const int smNode  = 180224;

    cudaFuncSetAttribute(mm2_layer<0>, cudaFuncAttributeMaxDynamicSharedMemorySize, smOpenN);
    cudaFuncSetAttribute(mm2_layer<4>, cudaFuncAttributeMaxDynamicSharedMemorySize, smOpenE);
    cudaFuncSetAttribute(mm2_layer<1>, cudaFuncAttributeMaxDynamicSharedMemorySize, smEdge);
    cudaFuncSetAttribute(node_layer<2>, cudaFuncAttributeMaxDynamicSharedMemorySize, smNode);
    cudaFuncSetAttribute(node_layer<5>, cudaFuncAttributeMaxDynamicSharedMemorySize, smNode);

    // Side stream + events, created once on the (uncaptured) correctness call.
    static cudaStream_t s2 = nullptr;
    static cudaEvent_t evF = nullptr, evJ = nullptr;
    if (s2 == nullptr) {
        cudaStreamCreateWithFlags(&s2, cudaStreamNonBlocking);
        cudaEventCreateWithFlags(&evF, cudaEventDisableTiming);
        cudaEventCreateWithFlags(&evJ, cudaEventDisableTiming);
    }

    const int gN64 = (NN + 63) / 64;   // 157
    const int gE64 = NE / 64;          // 2500

    // k_pack zeros g_cursor too; fork CSR build onto s2 (independent of opens/edge0).
    k_pack<<<37, 256>>>(KE1, KE2, KN1, KN2, K1Nopen, K2Nopen, K1Eopen, K2Eopen, KNclose);
    cudaEventRecord(evF, 0);
    cudaStreamWaitEvent(s2, evF, 0);
    k_deg<<<(NE + 255) / 256, 256, 0, s2>>>(iInd, jInd);
    k_scan<<<1, 1024, 0, s2>>>();
    k_fill<<<(NE + 255) / 256, 256, 0, s2>>>(iInd, jInd);
    cudaEventRecord(evJ, s2);

    // Main stream: opens + edge layer 0 overlap the CSR chain.
    mm2_layer<4><<<gE64, 128, smOpenE>>>(34, 0, xe_in, nullptr, nullptr, nullptr, NE);
    mm2_layer<0><<<gN64, 128, smOpenN>>>(32, 0, xn_in, nullptr, nullptr, nullptr, NN);

    for (int l = 0; l < 4; l++) {
        float* edst = (l == 3) ? (out + (size_t)64 * NN) : nullptr;
        mm2_layer<1><<<gE64, 128, smEdge>>>(l * 4, 0, nullptr, edst, iInd, jInd, NE);
        if (l == 0) cudaStreamWaitEvent(0, evJ, 0);   // CSR needed from first gather on
        k_gather<<<(NN + 31) / 32, 256>>>();
        if (l < 3)
            node_layer<2><<<gN64, 128, smNode>>>(16 + l * 4, (l + 1) * 4, nullptr);
        else
            node_layer<5><<<gN64, 128, smNode>>>(16 + l * 4, 36, out);
    }
}